// round 2
// baseline (speedup 1.0000x reference)
#include <cuda_runtime.h>
#include <cstddef>

// ---- problem constants ----
#define CH    256
#define CR    64          // CH / RED
#define GRP   16
#define CPG   16          // CH / GRP
#define KK    49          // K*K
#define O2    784         // KK * GRP
#define HH    64
#define WW    64
#define NPIX  4096        // HH*WW
#define BSZ   4

// ---- device scratch (allocation-free rule: __device__ globals) ----
__device__ float g_t[BSZ * CR * NPIX];        // 4 MB   reduce output
__device__ float g_kern[BSZ * O2 * NPIX];     // 51 MB  span output

// ============================================================================
// Kernel 1: t[b,o,p] = sum_c x[b,c,p] * wr[o,c] + br[o]
// grid (32 px-tiles of 128, BSZ), 256 threads.
// thread = (o_grp 0..7)*(px_grp 0..31): 8 outputs x 4 pixels in registers.
// ============================================================================
__global__ void reduce_kernel(const float* __restrict__ x,
                              const float* __restrict__ wr,
                              const float* __restrict__ br) {
    __shared__ float ws[64][65];   // ws[c_local][o], padded
    const int b   = blockIdx.y;
    const int pxb = blockIdx.x * 128;
    const int tid = threadIdx.x;
    const int og  = tid >> 5;
    const int pg  = tid & 31;
    const int px  = pxb + pg * 4;

    const float* xb = x + (size_t)b * CH * NPIX;
    float acc[8][4];
    #pragma unroll
    for (int i = 0; i < 8; ++i)
        #pragma unroll
        for (int j = 0; j < 4; ++j) acc[i][j] = 0.f;

    for (int cc = 0; cc < 4; ++cc) {            // 4 chunks of 64 channels
        // stage w chunk: wr[o*CH + cc*64 + cl] -> ws[cl][o]
        for (int i = tid; i < 64 * 64; i += 256) {
            int o = i >> 6, cl = i & 63;
            ws[cl][o] = wr[o * CH + cc * 64 + cl];
        }
        __syncthreads();
        #pragma unroll 4
        for (int cl = 0; cl < 64; ++cl) {
            const int c = cc * 64 + cl;
            const float4 xv = *reinterpret_cast<const float4*>(xb + (size_t)c * NPIX + px);
            #pragma unroll
            for (int oi = 0; oi < 8; ++oi) {
                const float w = ws[cl][og * 8 + oi];
                acc[oi][0] += w * xv.x;
                acc[oi][1] += w * xv.y;
                acc[oi][2] += w * xv.z;
                acc[oi][3] += w * xv.w;
            }
        }
        __syncthreads();
    }

    float* tb = g_t + (size_t)b * CR * NPIX;
    #pragma unroll
    for (int oi = 0; oi < 8; ++oi) {
        const int o = og * 8 + oi;
        const float bias = br[o];
        float4 v;
        v.x = acc[oi][0] + bias;
        v.y = acc[oi][1] + bias;
        v.z = acc[oi][2] + bias;
        v.w = acc[oi][3] + bias;
        *reinterpret_cast<float4*>(tb + (size_t)o * NPIX + px) = v;
    }
}

// ============================================================================
// Kernel 2: kern[b,o2,p] = sum_k wspan[o2,k] * t[b,k,p] + bspan[o2]
// grid (32 px-tiles of 128, 14 o2-chunks of 56, BSZ), 256 threads.
// thread = (o_grp 0..7)*(px_grp 0..31): 7 outputs x 4 pixels.
// ============================================================================
__global__ void span_kernel(const float* __restrict__ wspan,
                            const float* __restrict__ bspan) {
    __shared__ float ws[64][57];   // ws[k][o_local], padded
    const int b   = blockIdx.z;
    const int oc  = blockIdx.y;            // 0..13
    const int pxb = blockIdx.x * 128;
    const int tid = threadIdx.x;
    const int og  = tid >> 5;
    const int pg  = tid & 31;
    const int px  = pxb + pg * 4;

    // stage w chunk: wspan[(oc*56+ol)*64 + k] -> ws[k][ol]
    for (int i = tid; i < 56 * 64; i += 256) {
        int ol = i >> 6, k = i & 63;
        ws[k][ol] = wspan[(size_t)(oc * 56 + ol) * 64 + k];
    }
    __syncthreads();

    const float* tb = g_t + (size_t)b * CR * NPIX;
    float acc[7][4];
    #pragma unroll
    for (int i = 0; i < 7; ++i)
        #pragma unroll
        for (int j = 0; j < 4; ++j) acc[i][j] = 0.f;

    #pragma unroll 4
    for (int k = 0; k < 64; ++k) {
        const float4 tv = *reinterpret_cast<const float4*>(tb + (size_t)k * NPIX + px);
        #pragma unroll
        for (int oi = 0; oi < 7; ++oi) {
            const float w = ws[k][og * 7 + oi];
            acc[oi][0] += w * tv.x;
            acc[oi][1] += w * tv.y;
            acc[oi][2] += w * tv.z;
            acc[oi][3] += w * tv.w;
        }
    }

    float* kb = g_kern + (size_t)b * O2 * NPIX;
    #pragma unroll
    for (int oi = 0; oi < 7; ++oi) {
        const int o2 = oc * 56 + og * 7 + oi;
        const float bias = bspan[o2];
        float4 v;
        v.x = acc[oi][0] + bias;
        v.y = acc[oi][1] + bias;
        v.z = acc[oi][2] + bias;
        v.w = acc[oi][3] + bias;
        *reinterpret_cast<float4*>(kb + (size_t)o2 * NPIX + px) = v;
    }
}

// ============================================================================
// Kernel 3: out[b,c,y,x] = sum_{i,j} kern[b, g*49 + i*7+j, y, x] * x[b,c,y+i-3,x+j-3]
// grid (32 tiles [8 y-tiles x 4 x-tiles of 8x16 px], GRP, BSZ), 256 threads.
// thread = (c2 0..1)*(px 0..127): 8 channels x 1 pixel.
// ============================================================================
__global__ void inv_kernel(const float* __restrict__ x,
                           float* __restrict__ out) {
    __shared__ float xs[CPG][14][22];   // 16ch halo tile (8+6 rows, 16+6 cols)
    __shared__ float ks[KK][128];       // kernel values for this group/tile

    const int b  = blockIdx.z;
    const int g  = blockIdx.y;
    const int yt = blockIdx.x >> 2;     // 0..7
    const int xt = blockIdx.x & 3;      // 0..3
    const int y0 = yt * 8;
    const int x0 = xt * 16;
    const int tid = threadIdx.x;

    // load x halo for this group's 16 channels
    const float* xb = x + ((size_t)b * CH + g * CPG) * NPIX;
    for (int i = tid; i < CPG * 14 * 22; i += 256) {
        int c = i / (14 * 22);
        int r = i % (14 * 22);
        int yy = r / 22;
        int xx = r % 22;
        int gy = y0 + yy - 3;
        int gx = x0 + xx - 3;
        float v = 0.f;
        if (gy >= 0 && gy < HH && gx >= 0 && gx < WW)
            v = xb[(size_t)c * NPIX + gy * WW + gx];
        xs[c][yy][xx] = v;
    }
    // load kern tile
    const float* kb = g_kern + ((size_t)b * O2 + g * KK) * NPIX;
    for (int i = tid; i < KK * 128; i += 256) {
        int kk = i >> 7;
        int p  = i & 127;
        int yy = p >> 4;
        int xx = p & 15;
        ks[kk][p] = kb[(size_t)kk * NPIX + (y0 + yy) * WW + (x0 + xx)];
    }
    __syncthreads();

    const int c2 = tid >> 7;            // 0..1
    const int p  = tid & 127;
    const int yy = p >> 4;
    const int xx = p & 15;

    float acc[8];
    #pragma unroll
    for (int ci = 0; ci < 8; ++ci) acc[ci] = 0.f;

    for (int ti = 0; ti < 7; ++ti) {
        #pragma unroll
        for (int tj = 0; tj < 7; ++tj) {
            const float kv = ks[ti * 7 + tj][p];
            #pragma unroll
            for (int ci = 0; ci < 8; ++ci)
                acc[ci] += kv * xs[c2 * 8 + ci][yy + ti][xx + tj];
        }
    }

    float* ob = out + ((size_t)b * CH + g * CPG + c2 * 8) * NPIX;
    const int gp = (y0 + yy) * WW + (x0 + xx);
    #pragma unroll
    for (int ci = 0; ci < 8; ++ci)
        ob[(size_t)ci * NPIX + gp] = acc[ci];
}

// ============================================================================
extern "C" void kernel_launch(void* const* d_in, const int* in_sizes, int n_in,
                              void* d_out, int out_size) {
    const float* x    = (const float*)d_in[0];
    const float* wr   = (const float*)d_in[1];
    const float* br   = (const float*)d_in[2];
    const float* wsp  = (const float*)d_in[3];
    const float* bsp  = (const float*)d_in[4];
    float* out = (float*)d_out;

    reduce_kernel<<<dim3(32, BSZ), 256>>>(x, wr, br);
    span_kernel<<<dim3(32, 14, BSZ), 256>>>(wsp, bsp);
    inv_kernel<<<dim3(32, GRP, BSZ), 256>>>(x, out);
}

// round 4
// speedup vs baseline: 1.6784x; 1.6784x over previous
#include <cuda_runtime.h>
#include <cstddef>

// ---- problem constants ----
#define CH    256
#define CR    64          // CH / RED
#define GRP   16
#define CPG   16          // CH / GRP
#define KK    49          // K*K
#define O2    784         // KK * GRP
#define HH    64
#define WW    64
#define NPIX  4096        // HH*WW
#define BSZ   4

// ---- device scratch ----
__device__ float g_t[BSZ * CR * NPIX];        // 4 MB reduce output (L2-resident)

// ============================================================================
// Kernel 1: t[b,o,p] = sum_c x[b,c,p] * wr[o,c] + br[o]
// grid (64 px-tiles of 64, 2 o-chunks of 32, BSZ) = 512 blocks, 256 threads.
// thread = (og 0..7 -> 4 outs) x (pg 0..31 -> 2 px). Full 32x256 W slice in smem.
// ============================================================================
__global__ void __launch_bounds__(256) reduce_kernel(
        const float* __restrict__ x,
        const float* __restrict__ wr,
        const float* __restrict__ br) {
    __shared__ float4 ws4[32 * 64];          // ws[o_local][k] as float4 over k (32KB)
    const int b   = blockIdx.z;
    const int oc  = blockIdx.y;              // 0..1
    const int px0 = blockIdx.x * 64;
    const int tid = threadIdx.x;

    // stage weights: wr rows oc*32 .. oc*32+31, flat copy (row-major matches)
    const float4* wsrc = reinterpret_cast<const float4*>(wr + (size_t)oc * 32 * CH);
    for (int i = tid; i < 2048; i += 256) ws4[i] = wsrc[i];
    __syncthreads();

    const int og = tid >> 5;                 // 0..7
    const int pg = tid & 31;
    const int px = px0 + pg * 2;
    const float* xb = x + (size_t)b * CH * NPIX + px;

    float acc[4][2];
    #pragma unroll
    for (int i = 0; i < 4; ++i) { acc[i][0] = 0.f; acc[i][1] = 0.f; }

    #pragma unroll 4
    for (int k4 = 0; k4 < 64; ++k4) {
        const float2 x0 = *reinterpret_cast<const float2*>(xb + (size_t)(k4 * 4 + 0) * NPIX);
        const float2 x1 = *reinterpret_cast<const float2*>(xb + (size_t)(k4 * 4 + 1) * NPIX);
        const float2 x2 = *reinterpret_cast<const float2*>(xb + (size_t)(k4 * 4 + 2) * NPIX);
        const float2 x3 = *reinterpret_cast<const float2*>(xb + (size_t)(k4 * 4 + 3) * NPIX);
        #pragma unroll
        for (int oi = 0; oi < 4; ++oi) {
            const float4 wv = ws4[(og * 4 + oi) * 64 + k4];
            acc[oi][0] += wv.x * x0.x + wv.y * x1.x + wv.z * x2.x + wv.w * x3.x;
            acc[oi][1] += wv.x * x0.y + wv.y * x1.y + wv.z * x2.y + wv.w * x3.y;
        }
    }

    float* tb = g_t + (size_t)b * CR * NPIX + px;
    #pragma unroll
    for (int oi = 0; oi < 4; ++oi) {
        const int o = oc * 32 + og * 4 + oi;
        const float bias = br[o];
        float2 v; v.x = acc[oi][0] + bias; v.y = acc[oi][1] + bias;
        *reinterpret_cast<float2*>(tb + (size_t)o * NPIX) = v;
    }
}

// ============================================================================
// Kernel 2 (fused span + involution apply).
// Block = (tile 0..31 [2 rows x 64 cols = 128 px], g 0..15, b 0..3) = 2048 blocks.
// Phase A: ks[49][128] = Wspan_g[49][64] @ t_tile[64][128] + bias   (smem mini-GEMM)
// Phase B: out[c][p] = sum_{ti,tj} ks[ti*7+tj][p] * x[c][nbr(p,ti,tj)]
// Dynamic smem (70400 B): ks | union{ (ts + wss) , xs }
// ============================================================================
extern __shared__ float sm[];

__global__ void __launch_bounds__(256) fused_kernel(
        const float* __restrict__ x,
        const float* __restrict__ wspan,
        const float* __restrict__ bspan,
        float* __restrict__ out) {
    float* ks  = sm;                         // 49*128   = 6272 floats
    float* ts  = sm + 6272;                  // 64*128   = 8192 floats (phase A)
    float* wss = sm + 6272 + 8192;           // 49*64    = 3136 floats (phase A)
    float* xs  = sm + 6272;                  // 16*8*72  = 9216 floats (phase B alias)

    const int tile = blockIdx.x;             // 0..31
    const int g    = blockIdx.y;             // 0..15
    const int b    = blockIdx.z;             // 0..3
    const int tid  = threadIdx.x;
    const int p0g  = tile * 128;             // contiguous 128-px tile = 2 rows
    const int y0   = tile * 2;

    // ---- load t tile + wspan slice ----
    {
        float4* td = reinterpret_cast<float4*>(ts);
        const float* tsrc = g_t + (size_t)b * CR * NPIX + p0g;
        for (int i = tid; i < 2048; i += 256) {
            const int k = i >> 5, j = i & 31;
            td[i] = *reinterpret_cast<const float4*>(tsrc + (size_t)k * NPIX + j * 4);
        }
        const float4* wsrc = reinterpret_cast<const float4*>(wspan + (size_t)g * KK * 64);
        float4* wd = reinterpret_cast<float4*>(wss);
        for (int i = tid; i < 784; i += 256) wd[i] = wsrc[i];
    }
    __syncthreads();

    const int og = tid >> 5;                 // 0..7
    const int pg = tid & 31;

    // ---- Phase A: mini-GEMM 49x128x64 ----
    {
        float acc[7][4];
        #pragma unroll
        for (int i = 0; i < 7; ++i)
            #pragma unroll
            for (int j = 0; j < 4; ++j) acc[i][j] = 0.f;

        const float4* ts4 = reinterpret_cast<const float4*>(ts);
        const float4* ws4 = reinterpret_cast<const float4*>(wss);

        #pragma unroll 4
        for (int k4 = 0; k4 < 16; ++k4) {
            const float4 t0 = ts4[(k4 * 4 + 0) * 32 + pg];
            const float4 t1 = ts4[(k4 * 4 + 1) * 32 + pg];
            const float4 t2 = ts4[(k4 * 4 + 2) * 32 + pg];
            const float4 t3 = ts4[(k4 * 4 + 3) * 32 + pg];
            #pragma unroll
            for (int oi = 0; oi < 7; ++oi) {
                const int k  = oi * 8 + og;
                const int km = (k < KK) ? k : (KK - 1);     // clamp; store guarded
                const float4 wv = ws4[km * 16 + k4];
                acc[oi][0] += wv.x * t0.x + wv.y * t1.x + wv.z * t2.x + wv.w * t3.x;
                acc[oi][1] += wv.x * t0.y + wv.y * t1.y + wv.z * t2.y + wv.w * t3.y;
                acc[oi][2] += wv.x * t0.z + wv.y * t1.z + wv.z * t2.z + wv.w * t3.z;
                acc[oi][3] += wv.x * t0.w + wv.y * t1.w + wv.z * t2.w + wv.w * t3.w;
            }
        }
        #pragma unroll
        for (int oi = 0; oi < 7; ++oi) {
            const int k = oi * 8 + og;
            if (k < KK) {
                const float bias = bspan[g * KK + k];
                float4 v;
                v.x = acc[oi][0] + bias; v.y = acc[oi][1] + bias;
                v.z = acc[oi][2] + bias; v.w = acc[oi][3] + bias;
                *reinterpret_cast<float4*>(ks + k * 128 + pg * 4) = v;
            }
        }
    }
    __syncthreads();   // ks complete; ts/wss reads done -> safe to overwrite with xs

    // ---- load x halo: 16 ch x 8 rows x 72 cols (rows y0-3..y0+4, cols -3..68) ----
    {
        const float* xg = x + ((size_t)b * CH + g * CPG) * NPIX;
        for (int i = tid; i < CPG * 8 * 72; i += 256) {
            const int c  = i / 576;
            const int r  = (i % 576) / 72;
            const int xi = i % 72;
            const int gy = y0 + r - 3;
            const int gx = xi - 3;
            float v = 0.f;
            if ((unsigned)gy < HH && (unsigned)gx < WW)
                v = xg[(size_t)c * NPIX + gy * WW + gx];
            xs[i] = v;
        }
    }
    __syncthreads();

    // ---- Phase B: apply. thread = (cg 0..7 -> 2 ch) x (px4 0..31 -> 4 px) ----
    {
        const int px4 = tid & 31;
        const int cg  = tid >> 5;
        const int yy  = px4 >> 4;            // 0..1 (output row within tile)
        const int xx  = (px4 & 15) * 4;      // 0..60 (output col, 4-aligned)
        const int c0  = cg * 2;

        float acc[2][4];
        #pragma unroll
        for (int i = 0; i < 2; ++i)
            #pragma unroll
            for (int j = 0; j < 4; ++j) acc[i][j] = 0.f;

        const float4* ks4 = reinterpret_cast<const float4*>(ks);

        #pragma unroll
        for (int ti = 0; ti < 7; ++ti) {
            // register windows: cols xx..xx+11 of halo row (only xx..xx+9 used)
            float w0[12], w1[12];
            const float* r0 = xs + (size_t)(c0 * 8 + yy + ti) * 72 + xx;
            const float* r1 = xs + (size_t)((c0 + 1) * 8 + yy + ti) * 72 + xx;
            *reinterpret_cast<float4*>(w0 + 0) = *reinterpret_cast<const float4*>(r0 + 0);
            *reinterpret_cast<float4*>(w0 + 4) = *reinterpret_cast<const float4*>(r0 + 4);
            *reinterpret_cast<float4*>(w0 + 8) = *reinterpret_cast<const float4*>(r0 + 8);
            *reinterpret_cast<float4*>(w1 + 0) = *reinterpret_cast<const float4*>(r1 + 0);
            *reinterpret_cast<float4*>(w1 + 4) = *reinterpret_cast<const float4*>(r1 + 4);
            *reinterpret_cast<float4*>(w1 + 8) = *reinterpret_cast<const float4*>(r1 + 8);
            #pragma unroll
            for (int tj = 0; tj < 7; ++tj) {
                const float4 kv = ks4[(ti * 7 + tj) * 32 + px4];
                acc[0][0] += kv.x * w0[tj + 0];
                acc[0][1] += kv.y * w0[tj + 1];
                acc[0][2] += kv.z * w0[tj + 2];
                acc[0][3] += kv.w * w0[tj + 3];
                acc[1][0] += kv.x * w1[tj + 0];
                acc[1][1] += kv.y * w1[tj + 1];
                acc[1][2] += kv.z * w1[tj + 2];
                acc[1][3] += kv.w * w1[tj + 3];
            }
        }

        #pragma unroll
        for (int ci = 0; ci < 2; ++ci) {
            const int c = g * CPG + c0 + ci;
            float4 v;
            v.x = acc[ci][0]; v.y = acc[ci][1]; v.z = acc[ci][2]; v.w = acc[ci][3];
            *reinterpret_cast<float4*>(out + ((size_t)b * CH + c) * NPIX + p0g + px4 * 4) = v;
        }
    }
}

// ============================================================================
extern "C" void kernel_launch(void* const* d_in, const int* in_sizes, int n_in,
                              void* d_out, int out_size) {
    const float* x   = (const float*)d_in[0];
    const float* wr  = (const float*)d_in[1];
    const float* br  = (const float*)d_in[2];
    const float* wsp = (const float*)d_in[3];
    const float* bsp = (const float*)d_in[4];
    float* out = (float*)d_out;

    const int FUSED_SMEM = 70400;   // bytes
    cudaFuncSetAttribute(fused_kernel,
                         cudaFuncAttributeMaxDynamicSharedMemorySize, FUSED_SMEM);

    reduce_kernel<<<dim3(64, 2, BSZ), 256>>>(x, wr, br);
    fused_kernel<<<dim3(32, GRP, BSZ), 256, FUSED_SMEM>>>(x, wsp, bsp, out);
}